// round 2
// baseline (speedup 1.0000x reference)
#include <cuda_runtime.h>
#include <cuda_bf16.h>
#include <math.h>
#include <float.h>
#include <stdint.h>

// ---------------------------------------------------------------------------
// DeepRare: per-channel rarity collapses to a 6-entry LUT per channel.
// Passes: minmax -> dual hist + gidx(u8) -> per-channel tables -> proc sum
//         -> proc minmax -> threshold -> resize(240x240) -> final groups.
// ---------------------------------------------------------------------------

#define NCH 1472
#define GIDX_TOTAL 28108800
#define PROC_TOTAL 306912

__device__ unsigned g_cmin[NCH], g_cmax[NCH];
__device__ unsigned g_hist[NCH][6], g_hist2[NCH][6];
__device__ float g_M[NCH][6], g_Z[NCH];
__device__ unsigned char g_gidx[GIDX_TOTAL];
__device__ __align__(16) float g_proc[PROC_TOTAL];
__device__ unsigned g_pmin[5], g_pmax[5];
__device__ float g_resized[5 * 57600];
__device__ unsigned g_rmin[5], g_rmax[5];
__device__ float g_rsum[5];

__constant__ int c_procoff[5] = {0, 230400, 288000, 302400, 306000};
__constant__ int c_proclen[5] = {230400, 57600, 14400, 3600, 900};

// order-preserving float<->uint encoding for atomic min/max
__device__ __forceinline__ unsigned fenc(float f) {
    unsigned u = __float_as_uint(f);
    return (u & 0x80000000u) ? ~u : (u | 0x80000000u);
}
__device__ __forceinline__ float fdec(unsigned e) {
    return (e & 0x80000000u) ? __uint_as_float(e & 0x7fffffffu)
                             : __uint_as_float(~e);
}

__global__ void k_init() {
    int i = blockIdx.x * 256 + threadIdx.x;
    if (i < PROC_TOTAL) g_proc[i] = 0.f;
    if (i < NCH * 6) {
        ((unsigned*)g_hist)[i] = 0u;
        ((unsigned*)g_hist2)[i] = 0u;
    }
    if (i < NCH) { g_cmin[i] = 0xffffffffu; g_cmax[i] = 0u; }
    if (i < 5) {
        g_pmin[i] = 0xffffffffu; g_pmax[i] = 0u;
        g_rmin[i] = 0xffffffffu; g_rmax[i] = 0u;
        g_rsum[i] = 0.f;
    }
}

// -------- K1: per-channel min/max over zero-bordered channel ---------------
template <int H, int W>
__global__ void k_minmax(const float* __restrict__ in, int choff) {
    constexpr int HW = H * W;
    const int c = blockIdx.x;
    const int chunk = HW / gridDim.y;
    const int start = blockIdx.y * chunk;
    const float* p = in + (long)c * HW;
    float mn = FLT_MAX, mx = -FLT_MAX;
    for (int i = start + threadIdx.x; i < start + chunk; i += 256) {
        int y = i / W, x = i - y * W;
        float v = (y == 0 || x == 0 || y == H - 1 || x == W - 1) ? 0.f : p[i];
        mn = fminf(mn, v);
        mx = fmaxf(mx, v);
    }
    unsigned emn = __reduce_min_sync(0xffffffffu, fenc(mn));
    unsigned emx = __reduce_max_sync(0xffffffffu, fenc(mx));
    if ((threadIdx.x & 31) == 0) {
        atomicMin(&g_cmin[choff + c], emn);
        atomicMax(&g_cmax[choff + c], emx);
    }
}

// -------- K2: dual 6-bin histogram + gidx map (exact IEEE ops) -------------
template <int H, int W>
__global__ void k_hist(const float* __restrict__ in, int choff, long gidxoff) {
    constexpr int HW = H * W;
    const int c = blockIdx.x;
    const int chunk = HW / gridDim.y;
    const int start = blockIdx.y * chunk;
    const float* p = in + (long)c * HW;
    unsigned char* go = g_gidx + gidxoff + (long)c * HW;
    const float mn = fdec(g_cmin[choff + c]);
    const float mx = fdec(g_cmax[choff + c]);
    const float rng = mx - mn;
    const bool zr = (rng == 0.f);
    const float binw = 256.0f / 6.0f;
    unsigned long long pk1 = 0, pk2 = 0;   // 6 x 10-bit packed counters
    for (int i = start + threadIdx.x; i < start + chunk; i += 256) {
        int y = i / W, x = i - y * W;
        float v = (y == 0 || x == 0 || y == H - 1 || x == W - 1) ? 0.f : p[i];
        float chp = zr ? 0.f
                       : __fmul_rn(__fdiv_rn(__fsub_rn(v, mn), rng), 256.f);
        int bin = (int)floorf(__fdiv_rn(chp, binw));
        bin = min(5, max(0, bin));
        int g = (int)truncf(__fsub_rn(__fmul_rn(chp, 6.f), 1.f));
        g = min(5, max(0, g));
        pk1 += 1ull << (bin * 10);
        pk2 += 1ull << (g * 10);
        go[i] = (unsigned char)g;
    }
#pragma unroll
    for (int b = 0; b < 6; b++) {
        unsigned c1 = (unsigned)(pk1 >> (b * 10)) & 1023u;
        unsigned c2 = (unsigned)(pk2 >> (b * 10)) & 1023u;
        c1 = __reduce_add_sync(0xffffffffu, c1);
        c2 = __reduce_add_sync(0xffffffffu, c2);
        if ((threadIdx.x & 31) == 0) {
            if (c1) atomicAdd(&g_hist[choff + c][b], c1);
            if (c2) atomicAdd(&g_hist2[choff + c][b], c2);
        }
    }
}

// -------- K3: closed-form per-channel tables M (per gidx) and Z (border) ---
__global__ void k_stats_all() {
    int gc = blockIdx.x * 256 + threadIdx.x;
    if (gc >= NCH) return;
    int choff, H, W;
    if (gc < 64)       { choff = 0;   H = 480; W = 480; }
    else if (gc < 192) { choff = 64;  H = 240; W = 240; }
    else if (gc < 448) { choff = 192; H = 120; W = 120; }
    else if (gc < 960) { choff = 448; H = 60;  W = 60;  }
    else               { choff = 960; H = 30;  W = 30;  }
    const int c = gc - choff;       // channel index within layer
    const int N = H * W;
    const int Nb = 2 * (H + W) - 4;

    float mn = fdec(g_cmin[gc]), mx = fdec(g_cmax[gc]);
    float rng = mx - mn;

    float hl[6]; unsigned h2[6];
#pragma unroll
    for (int b = 0; b < 6; b++) {
        float pr = __fadd_rn(__fdiv_rn((float)g_hist[gc][b], (float)N), 1e-4f);
        hl[b] = -logf(pr);
        h2[b] = g_hist2[gc][b];
    }
    // dst = hl[gidx]; stats from gidx histogram (all pixels incl. border)
    float dmin = FLT_MAX, dmax = -FLT_MAX; double s = 0.0;
#pragma unroll
    for (int b = 0; b < 6; b++) if (h2[b]) {
        dmin = fminf(dmin, hl[b]); dmax = fmaxf(dmax, hl[b]);
        s += (double)h2[b] * (double)hl[b];
    }
    float drng = dmax - dmin;
    float L[6];
    if (drng == 0.f) {
#pragma unroll
        for (int b = 0; b < 6; b++) L[b] = 0.f;
    } else {
        float meann = ((float)(s / (double)N) - dmin) / drng;
        float t = 1.f - meann;          // dst_n.max() == 1 exactly
        float w1 = t * t;
#pragma unroll
        for (int b = 0; b < 6; b++) L[b] = (hl[b] - dmin) / drng * w1;
    }
    // border gidx (all border pixels have value 0 after zero_border)
    int gb = 0;
    if (rng != 0.f) {
        float chpb = __fmul_rn(__fdiv_rn(__fsub_rn(0.f, mn), rng), 256.f);
        int g = (int)truncf(__fsub_rn(__fmul_rn(chpb, 6.f), 1.f));
        gb = min(5, max(0, g));
    }
    // maps = r, border zeroed for c>0; second ponder -> final tables
    float mmin = FLT_MAX, mmax = -FLT_MAX; double s2 = 0.0;
#pragma unroll
    for (int b = 0; b < 6; b++) {
        unsigned cnt = h2[b];
        if (c > 0 && b == gb) cnt -= (unsigned)Nb;
        if (cnt) {
            mmin = fminf(mmin, L[b]); mmax = fmaxf(mmax, L[b]);
            s2 += (double)cnt * (double)L[b];
        }
    }
    if (c > 0) { mmin = fminf(mmin, 0.f); mmax = fmaxf(mmax, 0.f); }
    float mrng = mmax - mmin;
    if (mrng == 0.f) {
#pragma unroll
        for (int b = 0; b < 6; b++) g_M[gc][b] = 0.f;
        g_Z[gc] = 0.f;
    } else {
        float mmean = (float)(s2 / (double)N);
        float t = mmax - mmean;
        float w2 = t * t;
#pragma unroll
        for (int b = 0; b < 6; b++) g_M[gc][b] = (L[b] - mmin) / mrng * w2;
        g_Z[gc] = (0.f - mmin) / mrng * w2;
    }
}

// -------- K4: proc[p] += sum over channel slice of M[c][gidx] --------------
template <int H, int W>
__global__ void k_proc_quad(int choff, long gidxoff, int procoff, int csz) {
    constexpr int HW = H * W;
    constexpr int NQ = HW / 4;
    __shared__ float sM[64 * 6];
    __shared__ float sZ[64];
    const int cbeg = blockIdx.y * csz;
    for (int i = threadIdx.x; i < csz * 6; i += 256)
        sM[i] = ((const float*)g_M)[(choff + cbeg) * 6 + i];
    for (int i = threadIdx.x; i < csz; i += 256) sZ[i] = g_Z[choff + cbeg + i];
    __syncthreads();

    int q = blockIdx.x * 256 + threadIdx.x;
    if (q >= NQ) return;
    const uchar4* gp = (const uchar4*)(g_gidx + gidxoff);
    int p0 = q * 4;
    bool bf[4]; bool anyb = false;
#pragma unroll
    for (int k = 0; k < 4; k++) {
        int p = p0 + k; int y = p / W, x = p - y * W;
        bf[k] = (y == 0 || x == 0 || y == H - 1 || x == W - 1);
        anyb |= bf[k];
    }
    float a0 = 0.f, a1 = 0.f, a2 = 0.f, a3 = 0.f;
    if (!anyb) {
        for (int cc = 0; cc < csz; cc++) {
            uchar4 gv = gp[(long)(cbeg + cc) * NQ + q];
            const float* mc = sM + cc * 6;
            a0 += mc[gv.x]; a1 += mc[gv.y]; a2 += mc[gv.z]; a3 += mc[gv.w];
        }
    } else {
        for (int cc = 0; cc < csz; cc++) {
            uchar4 gv = gp[(long)(cbeg + cc) * NQ + q];
            const float* mc = sM + cc * 6;
            bool ch0 = (cbeg + cc) == 0;   // layer channel 0 keeps border
            float z = sZ[cc];
            a0 += (bf[0] && !ch0) ? z : mc[gv.x];
            a1 += (bf[1] && !ch0) ? z : mc[gv.y];
            a2 += (bf[2] && !ch0) ? z : mc[gv.z];
            a3 += (bf[3] && !ch0) ? z : mc[gv.w];
        }
    }
    float* pp = g_proc + procoff + p0;
    atomicAdd(pp + 0, a0); atomicAdd(pp + 1, a1);
    atomicAdd(pp + 2, a2); atomicAdd(pp + 3, a3);
}

// -------- K5: per-layer proc min/max ---------------------------------------
__global__ void k_procminmax() {
    const int l = blockIdx.y;
    const int off = c_procoff[l], len = c_proclen[l];
    float mn = FLT_MAX, mx = -FLT_MAX;
    for (int i = blockIdx.x * 256 + threadIdx.x; i < len; i += gridDim.x * 256) {
        float v = g_proc[off + i];
        mn = fminf(mn, v); mx = fmaxf(mx, v);
    }
    __shared__ unsigned smn[8], smx[8];
    unsigned emn = __reduce_min_sync(0xffffffffu, fenc(mn));
    unsigned emx = __reduce_max_sync(0xffffffffu, fenc(mx));
    if ((threadIdx.x & 31) == 0) {
        smn[threadIdx.x >> 5] = emn; smx[threadIdx.x >> 5] = emx;
    }
    __syncthreads();
    if (threadIdx.x == 0) {
        unsigned a = smn[0], b = smx[0];
#pragma unroll
        for (int w = 1; w < 8; w++) { a = min(a, smn[w]); b = max(b, smx[w]); }
        atomicMin(&g_pmin[l], a);
        atomicMax(&g_pmax[l], b);
    }
}

// -------- K6: normalize + threshold, in place ------------------------------
__global__ void k_thresh() {
    int i = blockIdx.x * 256 + threadIdx.x;
    if (i >= 306900) return;
    int l = (i < 230400) ? 0 : (i < 288000) ? 1 : (i < 302400) ? 2
          : (i < 306000) ? 3 : 4;
    float pmn = fdec(g_pmin[l]);
    float pmx = fdec(g_pmax[l]);
    float rng = pmx - pmn;
    float v = g_proc[i];
    float n = (rng == 0.f) ? 0.f : __fdiv_rn(__fsub_rn(v, pmn), rng);
    g_proc[i] = (n < 0.2f) ? 0.f : n;
}

// -------- K7: jax bilinear resize (antialias) + reductions -----------------
template <int S>
__global__ void k_resize(int procoff, int layer) {
    int idx = blockIdx.x * 256 + threadIdx.x;   // 57600 = 225*256 exact
    int oy = idx / 240, ox = idx - oy * 240;
    constexpr float inv = (float)S / 240.f;     // exact pow2 multiples
    constexpr float ks = (S > 240) ? inv : 1.f;
    constexpr float iks = 1.f / ks;
    float fy = (oy + 0.5f) * inv - 0.5f;
    float fx = (ox + 0.5f) * inv - 0.5f;
    int y0 = max(0, (int)ceilf(fy - ks)), y1 = min(S - 1, (int)floorf(fy + ks));
    int x0 = max(0, (int)ceilf(fx - ks)), x1 = min(S - 1, (int)floorf(fx + ks));
    float wy[4], wx[4];
    float sy = 0.f, sx = 0.f;
#pragma unroll
    for (int j = 0; j < 4; j++) {
        int yy = y0 + j;
        float w = (yy <= y1) ? fmaxf(0.f, 1.f - fabsf(fy - (float)yy) * iks) : 0.f;
        wy[j] = w; sy += w;
        int xx = x0 + j;
        float v = (xx <= x1) ? fmaxf(0.f, 1.f - fabsf(fx - (float)xx) * iks) : 0.f;
        wx[j] = v; sx += v;
    }
#pragma unroll
    for (int j = 0; j < 4; j++) {
        wy[j] = __fdiv_rn(wy[j], sy);
        wx[j] = __fdiv_rn(wx[j], sx);
    }
    const float* p = g_proc + procoff;
    float acc = 0.f;
#pragma unroll
    for (int jy = 0; jy < 4; jy++) {
        if (y0 + jy > y1) break;
        const float* row = p + (y0 + jy) * S;
        float r = 0.f;
#pragma unroll
        for (int jx = 0; jx < 4; jx++) {
            if (x0 + jx > x1) break;
            r += wx[jx] * row[x0 + jx];
        }
        acc += wy[jy] * r;
    }
    g_resized[layer * 57600 + idx] = acc;

    // block-level min/max/sum -> atomics
    __shared__ unsigned smn[8], smx[8];
    __shared__ float ssum[8];
    unsigned emn = __reduce_min_sync(0xffffffffu, fenc(acc));
    unsigned emx = __reduce_max_sync(0xffffffffu, fenc(acc));
    float ws = acc;
#pragma unroll
    for (int o = 16; o; o >>= 1) ws += __shfl_xor_sync(0xffffffffu, ws, o);
    if ((threadIdx.x & 31) == 0) {
        int w = threadIdx.x >> 5;
        smn[w] = emn; smx[w] = emx; ssum[w] = ws;
    }
    __syncthreads();
    if (threadIdx.x == 0) {
        unsigned a = smn[0], b = smx[0]; float s = ssum[0];
#pragma unroll
        for (int w = 1; w < 8; w++) {
            a = min(a, smn[w]); b = max(b, smx[w]); s += ssum[w];
        }
        atomicMin(&g_rmin[layer], a);
        atomicMax(&g_rmax[layer], b);
        atomicAdd(&g_rsum[layer], s);
    }
}

// -------- K8: final groups + sum -------------------------------------------
__global__ void k_final(float* __restrict__ out) {
    int idx = blockIdx.x * 256 + threadIdx.x;   // 57600
    float s = 0.f;
#pragma unroll
    for (int l = 0; l < 5; l++) {
        float v = g_resized[l * 57600 + idx];
        float rmn = fdec(g_rmin[l]);
        float rmx = fdec(g_rmax[l]);
        float rrng = rmx - rmn;
        float rmean = g_rsum[l] / 57600.f;
        float t = rmx - rmean;
        float w3 = t * t;
        float g = (rrng == 0.f || w3 == 0.f)
                  ? 0.f
                  : __fmul_rn(__fdiv_rn(__fsub_rn(v, rmn), rrng), 256.f);
        s += g;
        out[57600 + idx * 5 + l] = g;
    }
    out[idx] = s;
}

extern "C" void kernel_launch(void* const* d_in, const int* in_sizes, int n_in,
                              void* d_out, int out_size) {
    const float* l1 = (const float*)d_in[0];
    const float* l2 = (const float*)d_in[1];
    const float* l3 = (const float*)d_in[2];
    const float* l4 = (const float*)d_in[3];
    const float* l5 = (const float*)d_in[4];
    float* out = (float*)d_out;

    k_init<<<1200, 256>>>();

    k_minmax<480, 480><<<dim3(64, 8), 256>>>(l1, 0);
    k_minmax<240, 240><<<dim3(128, 2), 256>>>(l2, 64);
    k_minmax<120, 120><<<dim3(256, 1), 256>>>(l3, 192);
    k_minmax<60, 60><<<dim3(512, 1), 256>>>(l4, 448);
    k_minmax<30, 30><<<dim3(512, 1), 256>>>(l5, 960);

    k_hist<480, 480><<<dim3(64, 8), 256>>>(l1, 0, 0L);
    k_hist<240, 240><<<dim3(128, 2), 256>>>(l2, 64, 14745600L);
    k_hist<120, 120><<<dim3(256, 1), 256>>>(l3, 192, 22118400L);
    k_hist<60, 60><<<dim3(512, 1), 256>>>(l4, 448, 25804800L);
    k_hist<30, 30><<<dim3(512, 1), 256>>>(l5, 960, 27648000L);

    k_stats_all<<<6, 256>>>();

    k_proc_quad<480, 480><<<dim3(225, 1), 256>>>(0, 0L, 0, 64);
    k_proc_quad<240, 240><<<dim3(57, 4), 256>>>(64, 14745600L, 230400, 32);
    k_proc_quad<120, 120><<<dim3(15, 16), 256>>>(192, 22118400L, 288000, 16);
    k_proc_quad<60, 60><<<dim3(4, 32), 256>>>(448, 25804800L, 302400, 16);
    k_proc_quad<30, 30><<<dim3(1, 32), 256>>>(960, 27648000L, 306000, 16);

    k_procminmax<<<dim3(57, 5), 256>>>();
    k_thresh<<<1200, 256>>>();

    k_resize<480><<<225, 256>>>(0, 0);
    k_resize<240><<<225, 256>>>(230400, 1);
    k_resize<120><<<225, 256>>>(288000, 2);
    k_resize<60><<<225, 256>>>(302400, 3);
    k_resize<30><<<225, 256>>>(306000, 4);

    k_final<<<225, 256>>>(out);
}

// round 3
// speedup vs baseline: 2.1323x; 2.1323x over previous
#include <cuda_runtime.h>
#include <cuda_bf16.h>
#include <math.h>
#include <float.h>
#include <stdint.h>

// ---------------------------------------------------------------------------
// DeepRare: per-channel rarity collapses to a 6-entry LUT per channel.
// 8 launches: init -> minmax(all) -> hist+gidx(all) -> stats -> proc(all,
// fused pminmax for l1-3) -> mm45 -> resize(all, fused threshold) -> final.
// ---------------------------------------------------------------------------

#define NCH 1472
#define GIDX_TOTAL 28108800

__device__ unsigned g_cmin[NCH], g_cmax[NCH];
__device__ unsigned g_hist[NCH][6], g_hist2[NCH][6];
__device__ float g_M[NCH][6], g_Z[NCH];
__device__ __align__(16) unsigned char g_gidx[GIDX_TOTAL];
__device__ __align__(16) float g_proc[306912];
__device__ unsigned g_pmin[5], g_pmax[5];
__device__ float g_resized[5 * 57600];
__device__ unsigned g_rmin[5], g_rmax[5];
__device__ float g_rsum[5];

// order-preserving float<->uint encoding for atomic min/max
__device__ __forceinline__ unsigned fenc(float f) {
    unsigned u = __float_as_uint(f);
    return (u & 0x80000000u) ? ~u : (u | 0x80000000u);
}
__device__ __forceinline__ float fdec(unsigned e) {
    return (e & 0x80000000u) ? __uint_as_float(e & 0x7fffffffu)
                             : __uint_as_float(~e);
}

__global__ void k_init() {
    int i = blockIdx.x * 256 + threadIdx.x;
    if (i < NCH * 6) {
        ((unsigned*)g_hist)[i] = 0u;
        ((unsigned*)g_hist2)[i] = 0u;
    }
    if (i < NCH) { g_cmin[i] = 0xffffffffu; g_cmax[i] = 0u; }
    if (i < 4500) g_proc[302400 + i] = 0.f;   // l4+l5 (atomic-accumulated)
    if (i < 5) {
        g_pmin[i] = 0xffffffffu; g_pmax[i] = 0u;
        g_rmin[i] = 0xffffffffu; g_rmax[i] = 0u;
        g_rsum[i] = 0.f;
    }
}

// ---- shared: masked float4 load (borders -> 0), constexpr unrolled --------
template <int H, int W>
__device__ __forceinline__ void mask4(int fc, float4 v,
                                      float& v0, float& v1, float& v2, float& v3) {
    if constexpr (W % 4 == 0) {
        constexpr int W4 = W / 4;
        int row = fc / W4;
        int col = fc - row * W4;
        bool br = (row == 0) | (row == H - 1);
        v0 = (br | (col == 0))      ? 0.f : v.x;
        v1 = br                      ? 0.f : v.y;
        v2 = br                      ? 0.f : v.z;
        v3 = (br | (col == W4 - 1)) ? 0.f : v.w;
    } else {
        int e = fc * 4;
        int y0 = e / W, x0 = e - y0 * W;
        int y1 = (e+1) / W, x1 = (e+1) - y1 * W;
        int y2 = (e+2) / W, x2 = (e+2) - y2 * W;
        int y3 = (e+3) / W, x3 = (e+3) - y3 * W;
        v0 = ((y0==0)|(x0==0)|(y0==H-1)|(x0==W-1)) ? 0.f : v.x;
        v1 = ((y1==0)|(x1==0)|(y1==H-1)|(x1==W-1)) ? 0.f : v.y;
        v2 = ((y2==0)|(x2==0)|(y2==H-1)|(x2==W-1)) ? 0.f : v.z;
        v3 = ((y3==0)|(x3==0)|(y3==H-1)|(x3==W-1)) ? 0.f : v.w;
    }
}

// -------- K1: per-channel min/max over zero-bordered channel ---------------
template <int H, int W, int SLICES>
__device__ __forceinline__ void mm_layer(const float* __restrict__ in,
                                         int choff, int blk) {
    constexpr int HWf4 = H * W / 4;
    constexpr int SL = HWf4 / SLICES;
    constexpr int F4PT = (SL + 255) / 256;
    const int c = blk / SLICES;
    const int s = blk - c * SLICES;
    const float4* p4 = (const float4*)in + (size_t)c * HWf4 + s * SL;
    const int fbase = s * SL;
    float mn = FLT_MAX, mx = -FLT_MAX;
#pragma unroll
    for (int j = 0; j < F4PT; j++) {
        int fl = j * 256 + threadIdx.x;
        if (SL % 256 == 0 || fl < SL) {
            float4 v = p4[fl];
            float v0, v1, v2, v3;
            mask4<H, W>(fbase + fl, v, v0, v1, v2, v3);
            mn = fminf(mn, fminf(fminf(v0, v1), fminf(v2, v3)));
            mx = fmaxf(mx, fmaxf(fmaxf(v0, v1), fmaxf(v2, v3)));
        }
    }
    unsigned emn = __reduce_min_sync(0xffffffffu, fenc(mn));
    unsigned emx = __reduce_max_sync(0xffffffffu, fenc(mx));
    if ((threadIdx.x & 31) == 0) {
        atomicMin(&g_cmin[choff + c], emn);
        atomicMax(&g_cmax[choff + c], emx);
    }
}

__global__ __launch_bounds__(256) void k_minmax_all(
    const float* __restrict__ l1, const float* __restrict__ l2,
    const float* __restrict__ l3, const float* __restrict__ l4,
    const float* __restrict__ l5) {
    int b = blockIdx.x;
    if (b < 960)       mm_layer<480, 480, 15>(l1, 0, b);
    else if (b < 1472) mm_layer<240, 240, 4>(l2, 64, b - 960);
    else if (b < 1728) mm_layer<120, 120, 1>(l3, 192, b - 1472);
    else if (b < 2240) mm_layer<60, 60, 1>(l4, 448, b - 1728);
    else               mm_layer<30, 30, 1>(l5, 960, b - 2240);
}

// -------- K2: dual 6-bin histogram + gidx map (exact IEEE ops) -------------
template <int H, int W, int SLICES>
__device__ __forceinline__ void hist_layer(const float* __restrict__ in,
                                           int choff, size_t gidxoff, int blk) {
    constexpr int HWf4 = H * W / 4;
    constexpr int SL = HWf4 / SLICES;
    constexpr int F4PT = (SL + 255) / 256;
    const int c = blk / SLICES;
    const int s = blk - c * SLICES;
    const int gc = choff + c;
    const float4* p4 = (const float4*)in + (size_t)c * HWf4 + s * SL;
    uchar4* go = (uchar4*)(g_gidx + gidxoff) + (size_t)c * HWf4 + s * SL;
    const int fbase = s * SL;
    const float mn = fdec(g_cmin[gc]);
    const float mx = fdec(g_cmax[gc]);
    const float rng = mx - mn;
    const bool zr = (rng == 0.f);
    const float binw = 256.0f / 6.0f;
    unsigned long long pk1 = 0, pk2 = 0;   // 6 x 10-bit packed counters
#pragma unroll
    for (int j = 0; j < F4PT; j++) {
        int fl = j * 256 + threadIdx.x;
        if (SL % 256 == 0 || fl < SL) {
            float4 v = p4[fl];
            float vv[4];
            mask4<H, W>(fbase + fl, v, vv[0], vv[1], vv[2], vv[3]);
            unsigned gb[4];
#pragma unroll
            for (int k = 0; k < 4; k++) {
                float q = zr ? 0.f : __fdiv_rn(__fsub_rn(vv[k], mn), rng);
                float chp = __fmul_rn(q, 256.f);
                int bin = (int)floorf(__fdiv_rn(chp, binw));
                bin = min(5, max(0, bin));
                int g = (int)truncf(__fsub_rn(__fmul_rn(chp, 6.f), 1.f));
                g = min(5, max(0, g));
                pk1 += 1ull << (bin * 10);
                pk2 += 1ull << (g * 10);
                gb[k] = (unsigned)g;
            }
            go[fl] = make_uchar4(gb[0], gb[1], gb[2], gb[3]);
        }
    }
    __shared__ unsigned sh[12];
    if (threadIdx.x < 12) sh[threadIdx.x] = 0;
    __syncthreads();
#pragma unroll
    for (int b6 = 0; b6 < 6; b6++) {
        unsigned c1 = (unsigned)(pk1 >> (b6 * 10)) & 1023u;
        unsigned c2 = (unsigned)(pk2 >> (b6 * 10)) & 1023u;
        c1 = __reduce_add_sync(0xffffffffu, c1);
        c2 = __reduce_add_sync(0xffffffffu, c2);
        if ((threadIdx.x & 31) == 0) {
            if (c1) atomicAdd(&sh[b6], c1);
            if (c2) atomicAdd(&sh[6 + b6], c2);
        }
    }
    __syncthreads();
    if (threadIdx.x < 6 && sh[threadIdx.x])
        atomicAdd(&g_hist[gc][threadIdx.x], sh[threadIdx.x]);
    if (threadIdx.x >= 6 && threadIdx.x < 12 && sh[threadIdx.x])
        atomicAdd(&g_hist2[gc][threadIdx.x - 6], sh[threadIdx.x]);
}

__global__ __launch_bounds__(256) void k_hist_all(
    const float* __restrict__ l1, const float* __restrict__ l2,
    const float* __restrict__ l3, const float* __restrict__ l4,
    const float* __restrict__ l5) {
    int b = blockIdx.x;
    if (b < 960)       hist_layer<480, 480, 15>(l1, 0, 0, b);
    else if (b < 1472) hist_layer<240, 240, 4>(l2, 64, 14745600u, b - 960);
    else if (b < 1728) hist_layer<120, 120, 1>(l3, 192, 22118400u, b - 1472);
    else if (b < 2240) hist_layer<60, 60, 1>(l4, 448, 25804800u, b - 1728);
    else               hist_layer<30, 30, 1>(l5, 960, 27648000u, b - 2240);
}

// -------- K3: closed-form per-channel tables M (per gidx) and Z (border) ---
__global__ void k_stats_all() {
    int gc = blockIdx.x * 256 + threadIdx.x;
    if (gc >= NCH) return;
    int choff, H, W;
    if (gc < 64)       { choff = 0;   H = 480; W = 480; }
    else if (gc < 192) { choff = 64;  H = 240; W = 240; }
    else if (gc < 448) { choff = 192; H = 120; W = 120; }
    else if (gc < 960) { choff = 448; H = 60;  W = 60;  }
    else               { choff = 960; H = 30;  W = 30;  }
    const int c = gc - choff;
    const int N = H * W;
    const int Nb = 2 * (H + W) - 4;

    float mn = fdec(g_cmin[gc]), mx = fdec(g_cmax[gc]);
    float rng = mx - mn;

    float hl[6]; unsigned h2[6];
#pragma unroll
    for (int b = 0; b < 6; b++) {
        float pr = __fadd_rn(__fdiv_rn((float)g_hist[gc][b], (float)N), 1e-4f);
        hl[b] = -logf(pr);
        h2[b] = g_hist2[gc][b];
    }
    float dmin = FLT_MAX, dmax = -FLT_MAX; double s = 0.0;
#pragma unroll
    for (int b = 0; b < 6; b++) if (h2[b]) {
        dmin = fminf(dmin, hl[b]); dmax = fmaxf(dmax, hl[b]);
        s += (double)h2[b] * (double)hl[b];
    }
    float drng = dmax - dmin;
    float L[6];
    if (drng == 0.f) {
#pragma unroll
        for (int b = 0; b < 6; b++) L[b] = 0.f;
    } else {
        float meann = ((float)(s / (double)N) - dmin) / drng;
        float t = 1.f - meann;
        float w1 = t * t;
#pragma unroll
        for (int b = 0; b < 6; b++) L[b] = (hl[b] - dmin) / drng * w1;
    }
    int gb = 0;
    if (rng != 0.f) {
        float chpb = __fmul_rn(__fdiv_rn(__fsub_rn(0.f, mn), rng), 256.f);
        int g = (int)truncf(__fsub_rn(__fmul_rn(chpb, 6.f), 1.f));
        gb = min(5, max(0, g));
    }
    float mmin = FLT_MAX, mmax = -FLT_MAX; double s2 = 0.0;
#pragma unroll
    for (int b = 0; b < 6; b++) {
        unsigned cnt = h2[b];
        if (c > 0 && b == gb) cnt -= (unsigned)Nb;
        if (cnt) {
            mmin = fminf(mmin, L[b]); mmax = fmaxf(mmax, L[b]);
            s2 += (double)cnt * (double)L[b];
        }
    }
    if (c > 0) { mmin = fminf(mmin, 0.f); mmax = fmaxf(mmax, 0.f); }
    float mrng = mmax - mmin;
    if (mrng == 0.f) {
#pragma unroll
        for (int b = 0; b < 6; b++) g_M[gc][b] = 0.f;
        g_Z[gc] = 0.f;
    } else {
        float mmean = (float)(s2 / (double)N);
        float t = mmax - mmean;
        float w2 = t * t;
#pragma unroll
        for (int b = 0; b < 6; b++) g_M[gc][b] = (L[b] - mmin) / mrng * w2;
        g_Z[gc] = (0.f - mmin) / mrng * w2;
    }
}

// -------- K4: proc[p] = sum_c M[c][gidx]; fused pminmax when CS==C ---------
template <int C, int H, int W, int CS>
__device__ __forceinline__ void proc_layer(size_t gidxoff, int procoff,
                                           int choff, int pxblk, int cslice,
                                           int layer) {
    constexpr int HW = H * W;
    constexpr int NQ = HW / 4;
    __shared__ float sM[CS * 6];
    __shared__ float sZ[CS];
    const int cbeg = cslice * CS;
    for (int i = threadIdx.x; i < CS * 6; i += 256)
        sM[i] = ((const float*)g_M)[(choff + cbeg) * 6 + i];
    for (int i = threadIdx.x; i < CS; i += 256) sZ[i] = g_Z[choff + cbeg + i];
    __syncthreads();

    int q = pxblk * 256 + threadIdx.x;
    bool act = q < NQ;
    bool bf0 = false, bf1 = false, bf2 = false, bf3 = false;
    if (act) {
        if constexpr (W % 4 == 0) {
            constexpr int W4 = W / 4;
            int row = q / W4, col = q - row * W4;
            bool br = (row == 0) | (row == H - 1);
            bf0 = br | (col == 0); bf1 = br; bf2 = br;
            bf3 = br | (col == W4 - 1);
        } else {
            int e = q * 4;
#pragma unroll
            for (int k = 0; k < 4; k++) {
                int y = (e + k) / W, x = (e + k) - y * W;
                bool bb = (y == 0) | (x == 0) | (y == H - 1) | (x == W - 1);
                if (k == 0) bf0 = bb; else if (k == 1) bf1 = bb;
                else if (k == 2) bf2 = bb; else bf3 = bb;
            }
        }
    }
    bool anyb = __any_sync(0xffffffffu, act && (bf0 | bf1 | bf2 | bf3));
    float a0 = 0.f, a1 = 0.f, a2 = 0.f, a3 = 0.f;
    if (act) {
        const uchar4* gp = (const uchar4*)(g_gidx + gidxoff) + q;
        if (!anyb) {
#pragma unroll 8
            for (int cc = 0; cc < CS; cc++) {
                uchar4 gv = gp[(size_t)(cbeg + cc) * NQ - (size_t)cbeg * NQ + (size_t)cbeg * NQ];
                gv = gp[(size_t)(cbeg + cc) * NQ];
                const float* mc = sM + cc * 6;
                a0 += mc[gv.x]; a1 += mc[gv.y]; a2 += mc[gv.z]; a3 += mc[gv.w];
            }
        } else {
#pragma unroll 8
            for (int cc = 0; cc < CS; cc++) {
                uchar4 gv = gp[(size_t)(cbeg + cc) * NQ];
                const float* mc = sM + cc * 6;
                bool ch0 = (cbeg + cc) == 0;   // layer ch 0 keeps border
                float z = sZ[cc];
                a0 += (bf0 && !ch0) ? z : mc[gv.x];
                a1 += (bf1 && !ch0) ? z : mc[gv.y];
                a2 += (bf2 && !ch0) ? z : mc[gv.z];
                a3 += (bf3 && !ch0) ? z : mc[gv.w];
            }
        }
        if constexpr (CS == C) {
            ((float4*)(g_proc + procoff))[q] = make_float4(a0, a1, a2, a3);
        } else {
            float* pp = g_proc + procoff + q * 4;
            atomicAdd(pp + 0, a0); atomicAdd(pp + 1, a1);
            atomicAdd(pp + 2, a2); atomicAdd(pp + 3, a3);
        }
    }
    if constexpr (CS == C) {
        float vmn = act ? fminf(fminf(a0, a1), fminf(a2, a3)) : FLT_MAX;
        float vmx = act ? fmaxf(fmaxf(a0, a1), fmaxf(a2, a3)) : -FLT_MAX;
        __shared__ unsigned smn[8], smx[8];
        unsigned emn = __reduce_min_sync(0xffffffffu, fenc(vmn));
        unsigned emx = __reduce_max_sync(0xffffffffu, fenc(vmx));
        if ((threadIdx.x & 31) == 0) {
            smn[threadIdx.x >> 5] = emn; smx[threadIdx.x >> 5] = emx;
        }
        __syncthreads();
        if (threadIdx.x == 0) {
            unsigned a = smn[0], b = smx[0];
#pragma unroll
            for (int w = 1; w < 8; w++) { a = min(a, smn[w]); b = max(b, smx[w]); }
            atomicMin(&g_pmin[layer], a);
            atomicMax(&g_pmax[layer], b);
        }
    }
}

__global__ __launch_bounds__(256) void k_proc_all() {
    int b = blockIdx.x;
    if (b < 225)       proc_layer<64, 480, 480, 64>(0, 0, 0, b, 0, 0);
    else if (b < 282)  proc_layer<128, 240, 240, 128>(14745600u, 230400, 64, b - 225, 0, 1);
    else if (b < 297)  proc_layer<256, 120, 120, 256>(22118400u, 288000, 192, b - 282, 0, 2);
    else if (b < 329) { int i = b - 297;
                        proc_layer<512, 60, 60, 64>(25804800u, 302400, 448, i & 3, i >> 2, 3); }
    else               proc_layer<512, 30, 30, 64>(27648000u, 306000, 960, 0, b - 329, 4);
}

// -------- K5: pmin/pmax for l4,l5 (atomic-accumulated proc) ----------------
__global__ void k_mm45() {
    int b = blockIdx.x;
    int off = (b < 4) ? 302400 + b * 900 : 306000;
    int layer = (b < 4) ? 3 : 4;
    float mn = FLT_MAX, mx = -FLT_MAX;
    for (int i = threadIdx.x; i < 900; i += 256) {
        float v = g_proc[off + i];
        mn = fminf(mn, v); mx = fmaxf(mx, v);
    }
    __shared__ unsigned smn[8], smx[8];
    unsigned emn = __reduce_min_sync(0xffffffffu, fenc(mn));
    unsigned emx = __reduce_max_sync(0xffffffffu, fenc(mx));
    if ((threadIdx.x & 31) == 0) {
        smn[threadIdx.x >> 5] = emn; smx[threadIdx.x >> 5] = emx;
    }
    __syncthreads();
    if (threadIdx.x == 0) {
        unsigned a = smn[0], bb = smx[0];
#pragma unroll
        for (int w = 1; w < 8; w++) { a = min(a, smn[w]); bb = max(bb, smx[w]); }
        atomicMin(&g_pmin[layer], a);
        atomicMax(&g_pmax[layer], bb);
    }
}

// -------- K6: resize (jax bilinear, antialias) + fused normalize/threshold -
template <int S>
__device__ __forceinline__ void resize_layer(int b, int procoff, int layer) {
    int idx = b * 256 + threadIdx.x;   // 57600 = 225*256 exact
    int oy = idx / 240, ox = idx - oy * 240;
    float pmn = fdec(g_pmin[layer]);
    float pmx = fdec(g_pmax[layer]);
    float prng = pmx - pmn;
    constexpr float inv = (float)S / 240.f;
    constexpr float ks = (S > 240) ? inv : 1.f;
    constexpr float iks = 1.f / ks;
    float fy = (oy + 0.5f) * inv - 0.5f;
    float fx = (ox + 0.5f) * inv - 0.5f;
    int y0 = max(0, (int)ceilf(fy - ks)), y1 = min(S - 1, (int)floorf(fy + ks));
    int x0 = max(0, (int)ceilf(fx - ks)), x1 = min(S - 1, (int)floorf(fx + ks));
    float wy[4], wx[4];
    float sy = 0.f, sx = 0.f;
#pragma unroll
    for (int j = 0; j < 4; j++) {
        int yy = y0 + j;
        float w = (yy <= y1) ? fmaxf(0.f, 1.f - fabsf(fy - (float)yy) * iks) : 0.f;
        wy[j] = w; sy += w;
        int xx = x0 + j;
        float v = (xx <= x1) ? fmaxf(0.f, 1.f - fabsf(fx - (float)xx) * iks) : 0.f;
        wx[j] = v; sx += v;
    }
#pragma unroll
    for (int j = 0; j < 4; j++) {
        wy[j] = __fdiv_rn(wy[j], sy);
        wx[j] = __fdiv_rn(wx[j], sx);
    }
    const float* p = g_proc + procoff;
    float acc = 0.f;
#pragma unroll
    for (int jy = 0; jy < 4; jy++) {
        if (y0 + jy > y1) break;
        const float* row = p + (y0 + jy) * S;
        float r = 0.f;
#pragma unroll
        for (int jx = 0; jx < 4; jx++) {
            if (x0 + jx > x1) break;
            float v = row[x0 + jx];
            float n = (prng == 0.f) ? 0.f : __fdiv_rn(__fsub_rn(v, pmn), prng);
            n = (n < 0.2f) ? 0.f : n;
            r += wx[jx] * n;
        }
        acc += wy[jy] * r;
    }
    g_resized[layer * 57600 + idx] = acc;

    __shared__ unsigned smn[8], smx[8];
    __shared__ float ssum[8];
    unsigned emn = __reduce_min_sync(0xffffffffu, fenc(acc));
    unsigned emx = __reduce_max_sync(0xffffffffu, fenc(acc));
    float wsum = acc;
#pragma unroll
    for (int o = 16; o; o >>= 1) wsum += __shfl_xor_sync(0xffffffffu, wsum, o);
    if ((threadIdx.x & 31) == 0) {
        int w = threadIdx.x >> 5;
        smn[w] = emn; smx[w] = emx; ssum[w] = wsum;
    }
    __syncthreads();
    if (threadIdx.x == 0) {
        unsigned a = smn[0], bb = smx[0]; float s = ssum[0];
#pragma unroll
        for (int w = 1; w < 8; w++) {
            a = min(a, smn[w]); bb = max(bb, smx[w]); s += ssum[w];
        }
        atomicMin(&g_rmin[layer], a);
        atomicMax(&g_rmax[layer], bb);
        atomicAdd(&g_rsum[layer], s);
    }
}

__global__ __launch_bounds__(256) void k_resize_all() {
    int b = blockIdx.x;
    if (b < 225)      resize_layer<480>(b, 0, 0);
    else if (b < 450) resize_layer<240>(b - 225, 230400, 1);
    else if (b < 675) resize_layer<120>(b - 450, 288000, 2);
    else if (b < 900) resize_layer<60>(b - 675, 302400, 3);
    else              resize_layer<30>(b - 900, 306000, 4);
}

// -------- K7: final groups + sum -------------------------------------------
__global__ void k_final(float* __restrict__ out) {
    int idx = blockIdx.x * 256 + threadIdx.x;   // 57600
    float s = 0.f;
#pragma unroll
    for (int l = 0; l < 5; l++) {
        float v = g_resized[l * 57600 + idx];
        float rmn = fdec(g_rmin[l]);
        float rmx = fdec(g_rmax[l]);
        float rrng = rmx - rmn;
        float rmean = g_rsum[l] / 57600.f;
        float t = rmx - rmean;
        float w3 = t * t;
        float g = (rrng == 0.f || w3 == 0.f)
                  ? 0.f
                  : __fmul_rn(__fdiv_rn(__fsub_rn(v, rmn), rrng), 256.f);
        s += g;
        out[57600 + idx * 5 + l] = g;
    }
    out[idx] = s;
}

extern "C" void kernel_launch(void* const* d_in, const int* in_sizes, int n_in,
                              void* d_out, int out_size) {
    const float* l1 = (const float*)d_in[0];
    const float* l2 = (const float*)d_in[1];
    const float* l3 = (const float*)d_in[2];
    const float* l4 = (const float*)d_in[3];
    const float* l5 = (const float*)d_in[4];
    float* out = (float*)d_out;

    k_init<<<35, 256>>>();
    k_minmax_all<<<2752, 256>>>(l1, l2, l3, l4, l5);
    k_hist_all<<<2752, 256>>>(l1, l2, l3, l4, l5);
    k_stats_all<<<6, 256>>>();
    k_proc_all<<<337, 256>>>();
    k_mm45<<<5, 256>>>();
    k_resize_all<<<1125, 256>>>();
    k_final<<<225, 256>>>(out);
}